// round 2
// baseline (speedup 1.0000x reference)
#include <cuda_runtime.h>
#include <cuda_bf16.h>

// LIF scan: out[b,0,h]=0; for k=1..T-1:
//   reset = (V > 1)
//   V     = 0.9*V + z[b,k-1,h] - reset
//   out[b,k,h] = (V > 1) ? 1 : 0
//
// One thread per (b,h) chain. 32*512 = 16384 threads.
// Loads are independent of the recurrence -> unroll for MLP.

#define B 32
#define T 1024
#define H 512
#define BETA 0.9f
#define THR 1.0f

__global__ __launch_bounds__(128, 1)
void lif_kernel(const float* __restrict__ z, float* __restrict__ out) {
    const int tid = blockIdx.x * blockDim.x + threadIdx.x;  // 0..16383
    const int b = tid >> 9;          // tid / 512
    const int h = tid & 511;         // tid % 512

    const float* zp = z   + (size_t)b * T * H + h;
    float*       op = out + (size_t)b * T * H + h;

    // k = 0 output is zero (d_out is poisoned, must write).
    op[0] = 0.0f;

    float V = 0.0f;

    // steps k = 1 .. 1023 ; input z[b, k-1, h]
    #pragma unroll 8
    for (int k = 1; k < T; ++k) {
        float zin = zp[(k - 1) * H];        // independent of V -> prefetchable
        float zm1 = zin - THR;              // off critical path
        // critical path: FSETP(pred) -> FSEL -> FFMA  (~12 cyc)
        float inj = (V > THR) ? zm1 : zin;  // z - reset*thr
        V = fmaf(BETA, V, inj);
        op[k * H] = (V > THR) ? 1.0f : 0.0f;
    }
}

extern "C" void kernel_launch(void* const* d_in, const int* in_sizes, int n_in,
                              void* d_out, int out_size) {
    const float* z = (const float*)d_in[0];
    float* out = (float*)d_out;
    lif_kernel<<<(B * H) / 128, 128>>>(z, out);
}